// round 11
// baseline (speedup 1.0000x reference)
#include <cuda_runtime.h>
#include <math.h>

#define CC    256
#define NNODE 768
#define TT    12
#define NT    9216
#define NPOS  73728
#define SCALE 0.125f
#define LNEPS 1e-6f

__device__ float g_x1t [NPOS * 256];
__device__ float g_qkvf[(size_t)NPOS * 448];
__device__ float g_P   [(size_t)96 * 768 * 768];
__device__ float g_H   [NPOS * 128];
__device__ float g_xmid[NPOS * 256];
__device__ float g_x2  [NPOS * 256];
__device__ float g_y   [(size_t)NPOS * 1024];
__device__ float g_z   [(size_t)NPOS * 512];
__device__ float g_wqkvf[256 * 448];
__device__ float g_b448 [448];
__device__ float g_wproj[128 * 256];
__device__ float g_w1p  [256 * 1024];
__device__ float g_w2p  [512 * 256];

// ---------------- weight packing (k-major) ----------------
__global__ void pack_weights(const float* __restrict__ Wnq, const float* __restrict__ Wnk,
                             const float* __restrict__ Wtq, const float* __restrict__ Wtk,
                             const float* __restrict__ bnq, const float* __restrict__ bnk,
                             const float* __restrict__ btq, const float* __restrict__ btk,
                             const float* __restrict__ v_w, const float* __restrict__ v_b,
                             const float* __restrict__ fcv_w, const float* __restrict__ fcv_b,
                             const float* __restrict__ proj_w,
                             const float* __restrict__ ffn_w1, const float* __restrict__ ffn_w2) {
    int t = blockIdx.x * blockDim.x + threadIdx.x;
    int stride = gridDim.x * blockDim.x;
    for (int i = t; i < 256 * 448; i += stride) {
        int c = i / 448, o = i % 448; float v;
        if      (o < 64)  v = Wnq[c * 64 + o];
        else if (o < 128) v = Wnk[c * 64 + (o - 64)];
        else if (o < 192) v = Wtq[c * 64 + (o - 128)];
        else if (o < 256) v = Wtk[c * 64 + (o - 192)];
        else if (o < 320) v = v_w[(o - 256) * 256 + c];
        else              v = fcv_w[(o - 320) * 256 + c];
        g_wqkvf[i] = v;
    }
    for (int o = t; o < 448; o += stride) {
        float v;
        if      (o < 64)  v = bnq[o];
        else if (o < 128) v = bnk[o - 64];
        else if (o < 192) v = btq[o - 128];
        else if (o < 256) v = btk[o - 192];
        else if (o < 320) v = v_b[o - 256];
        else              v = fcv_b[o - 320];
        g_b448[o] = v;
    }
    for (int i = t; i < 128 * 256; i += stride) { int k = i / 256, o = i % 256; g_wproj[i] = proj_w[o * 128 + k]; }
    for (int i = t; i < 256 * 1024; i += stride) { int k = i / 1024, o = i % 1024; g_w1p[i] = ffn_w1[o * 256 + k]; }
    for (int i = t; i < 512 * 256; i += stride) { int k = i / 256, o = i % 256; g_w2p[i] = ffn_w2[o * 512 + k]; }
}

// ---------------- LN1 + transpose to position-major ----------------
__global__ __launch_bounds__(256) void ln1_kernel(const float* __restrict__ x,
                                                  const float* __restrict__ w,
                                                  const float* __restrict__ b) {
    __shared__ float s[256 * 33];
    __shared__ float psum[256], psq[256];
    __shared__ float mq[32], rq[32];
    int t = threadIdx.x;
    int p0 = blockIdx.x * 32;
    int bidx = p0 / NT;
    int pp0 = p0 - bidx * NT;
    const float* xb = x + (size_t)bidx * CC * NT + pp0;
#pragma unroll
    for (int i = 0; i < 32; i++) {
        int e = t + i * 256;
        int c = e >> 5, q = e & 31;
        s[c * 33 + q] = xb[(size_t)c * NT + q];
    }
    __syncthreads();
    {
        int q = t & 31, part = t >> 5;
        float sm = 0.f, sq = 0.f;
#pragma unroll
        for (int j = 0; j < 32; j++) {
            float v = s[(part * 32 + j) * 33 + q];
            sm += v; sq += v * v;
        }
        psum[t] = sm; psq[t] = sq;
    }
    __syncthreads();
    if (t < 32) {
        float S = 0.f, Q = 0.f;
#pragma unroll
        for (int p = 0; p < 8; p++) { S += psum[p * 32 + t]; Q += psq[p * 32 + t]; }
        float mean = S * (1.f / 256.f);
        float var  = Q * (1.f / 256.f) - mean * mean;
        mq[t] = mean;
        rq[t] = rsqrtf(fmaxf(var, 0.f) + LNEPS);
    }
    __syncthreads();
    int wrp = t >> 5, lane = t & 31;
#pragma unroll
    for (int u = 0; u < 4; u++) {
        int q = wrp * 4 + u;
        float mean = mq[q], rstd = rq[q];
        float* outr = g_x1t + (size_t)(p0 + q) * 256;
#pragma unroll
        for (int j = 0; j < 8; j++) {
            int c = lane + j * 32;
            outr[c] = (s[c * 33 + q] - mean) * rstd * __ldg(&w[c]) + __ldg(&b[c]);
        }
    }
}

// ---------------- LN2 on position-major rows ----------------
__global__ __launch_bounds__(256) void ln2_kernel(const float* __restrict__ w,
                                                  const float* __restrict__ b) {
    int row = blockIdx.x * 8 + (threadIdx.x >> 5);
    int lane = threadIdx.x & 31;
    const float4* r4 = (const float4*)(g_xmid + (size_t)row * 256);
    float4 v0 = r4[lane * 2];
    float4 v1 = r4[lane * 2 + 1];
    float sm = v0.x + v0.y + v0.z + v0.w + v1.x + v1.y + v1.z + v1.w;
    float sq = v0.x*v0.x + v0.y*v0.y + v0.z*v0.z + v0.w*v0.w
             + v1.x*v1.x + v1.y*v1.y + v1.z*v1.z + v1.w*v1.w;
#pragma unroll
    for (int o = 16; o; o >>= 1) {
        sm += __shfl_xor_sync(0xffffffffu, sm, o);
        sq += __shfl_xor_sync(0xffffffffu, sq, o);
    }
    float mean = sm * (1.f / 256.f);
    float var  = sq * (1.f / 256.f) - mean * mean;
    float rstd = rsqrtf(fmaxf(var, 0.f) + LNEPS);
    const float4* w4 = (const float4*)w;
    const float4* b4 = (const float4*)b;
    float4* o4 = (float4*)(g_x2 + (size_t)row * 256);
    float4 ww = w4[lane * 2], bb = b4[lane * 2], r;
    r.x = (v0.x - mean) * rstd * ww.x + bb.x;
    r.y = (v0.y - mean) * rstd * ww.y + bb.y;
    r.z = (v0.z - mean) * rstd * ww.z + bb.z;
    r.w = (v0.w - mean) * rstd * ww.w + bb.w;
    o4[lane * 2] = r;
    ww = w4[lane * 2 + 1]; bb = b4[lane * 2 + 1];
    r.x = (v1.x - mean) * rstd * ww.x + bb.x;
    r.y = (v1.y - mean) * rstd * ww.y + bb.y;
    r.z = (v1.z - mean) * rstd * ww.z + bb.z;
    r.w = (v1.w - mean) * rstd * ww.w + bb.w;
    o4[lane * 2 + 1] = r;
}

// ---------------- SGEMM core: BM=128 BN=64 BK=16, 256thr, 8x4/thr ----------------
__device__ __forceinline__ void mm_inner(float As[][132], float Bs[][68],
                                         float acc[8][4], int tx, int ty) {
#pragma unroll
    for (int kk = 0; kk < 16; kk++) {
        float4 a0 = *(const float4*)&As[kk][ty * 8];
        float4 a1 = *(const float4*)&As[kk][ty * 8 + 4];
        float4 b0 = *(const float4*)&Bs[kk][tx * 4];
        float av[8] = {a0.x, a0.y, a0.z, a0.w, a1.x, a1.y, a1.z, a1.w};
        float bv[4] = {b0.x, b0.y, b0.z, b0.w};
#pragma unroll
        for (int ii = 0; ii < 8; ii++) {
            float a = av[ii];
#pragma unroll
            for (int jj = 0; jj < 4; jj++) acc[ii][jj] = fmaf(a, bv[jj], acc[ii][jj]);
        }
    }
}

__device__ __forceinline__ void gemm_bias_body(const float* __restrict__ A,
                                               const float* __restrict__ W,
                                               const float* __restrict__ bias,
                                               float* __restrict__ out,
                                               int Nn, int K) {
    __shared__ float As[16][132];
    __shared__ float Bs[16][68];
    float acc[8][4] = {};
    int t = threadIdx.x, tx = t & 15, ty = t >> 4;
    int m0 = blockIdx.x * 128, n0 = blockIdx.y * 64;
    for (int k0 = 0; k0 < K; k0 += 16) {
#pragma unroll
        for (int e = 0; e < 2; e++) {
            int f = t + e * 256;
            int row = f >> 2, kg = f & 3;
            float4 v = *(const float4*)&A[(size_t)(m0 + row) * K + k0 + kg * 4];
            As[kg * 4 + 0][row] = v.x; As[kg * 4 + 1][row] = v.y;
            As[kg * 4 + 2][row] = v.z; As[kg * 4 + 3][row] = v.w;
        }
        {
            int kr = t >> 4, ng = t & 15;
            *(float4*)&Bs[kr][ng * 4] = *(const float4*)&W[(size_t)(k0 + kr) * Nn + n0 + ng * 4];
        }
        __syncthreads();
        mm_inner(As, Bs, acc, tx, ty);
        __syncthreads();
    }
    int n = n0 + tx * 4;
    float4 bb = *(const float4*)&bias[n];
#pragma unroll
    for (int ii = 0; ii < 8; ii++) {
        int m = m0 + ty * 8 + ii;
        *(float4*)&out[(size_t)m * Nn + n] =
            make_float4(acc[ii][0] + bb.x, acc[ii][1] + bb.y, acc[ii][2] + bb.z, acc[ii][3] + bb.w);
    }
}

__global__ __launch_bounds__(256) void gemm_qkvf_kernel() {
    gemm_bias_body(g_x1t, g_wqkvf, g_b448, g_qkvf, 448, 256);
}
__global__ __launch_bounds__(256) void gemm_ffn1_kernel(const float* __restrict__ b1) {
    gemm_bias_body(g_x2, g_w1p, b1, g_y, 1024, 256);
}

// ---------------- node attn scores: S = Qn Kn^T * scale + Bn ----------------
__global__ __launch_bounds__(256) void gemm_s_kernel(const float* __restrict__ Bn) {
    __shared__ float As[16][132];
    __shared__ float Bs[16][68];
    float acc[8][4] = {};
    int t = threadIdx.x, tx = t & 15, ty = t >> 4;
    int m0 = blockIdx.x * 128, n0 = blockIdx.y * 64;
    int bt = blockIdx.z;
    int bb_ = bt / 12, ttime = bt - bb_ * 12;
    int rb = bb_ * NT + ttime;
    for (int k0 = 0; k0 < 64; k0 += 16) {
#pragma unroll
        for (int e = 0; e < 2; e++) {
            int f = t + e * 256;
            int row = f >> 2, kg = f & 3;
            float4 v = *(const float4*)&g_qkvf[(size_t)(rb + (m0 + row) * 12) * 448 + k0 + kg * 4];
            As[kg * 4 + 0][row] = v.x; As[kg * 4 + 1][row] = v.y;
            As[kg * 4 + 2][row] = v.z; As[kg * 4 + 3][row] = v.w;
        }
        {
            int jl = t >> 2, kg = t & 3;
            float4 v = *(const float4*)&g_qkvf[(size_t)(rb + (n0 + jl) * 12) * 448 + 64 + k0 + kg * 4];
            Bs[kg * 4 + 0][jl] = v.x; Bs[kg * 4 + 1][jl] = v.y;
            Bs[kg * 4 + 2][jl] = v.z; Bs[kg * 4 + 3][jl] = v.w;
        }
        __syncthreads();
        mm_inner(As, Bs, acc, tx, ty);
        __syncthreads();
    }
    float* Pb = g_P + (size_t)bt * 589824;
    int n = n0 + tx * 4;
#pragma unroll
    for (int ii = 0; ii < 8; ii++) {
        int i = m0 + ty * 8 + ii;
        float4 bnv = *(const float4*)&Bn[(size_t)i * 768 + n];
        *(float4*)&Pb[(size_t)i * 768 + n] =
            make_float4(acc[ii][0] * SCALE + bnv.x, acc[ii][1] * SCALE + bnv.y,
                        acc[ii][2] * SCALE + bnv.z, acc[ii][3] * SCALE + bnv.w);
    }
}

// ---------------- row softmax * adj in place ----------------
__global__ __launch_bounds__(256) void softmax_adj_kernel(const float* __restrict__ adj) {
    __shared__ float red[8];
    size_t r = blockIdx.x;
    float* row = g_P + r * 768;
    const float* arow = adj + r * 768;
    int t = threadIdx.x;
    float v[3];
    float mx = -1e30f;
#pragma unroll
    for (int e = 0; e < 3; e++) { v[e] = row[t + e * 256]; mx = fmaxf(mx, v[e]); }
#pragma unroll
    for (int o = 16; o; o >>= 1) mx = fmaxf(mx, __shfl_xor_sync(0xffffffffu, mx, o));
    if ((t & 31) == 0) red[t >> 5] = mx;
    __syncthreads();
    mx = red[0];
#pragma unroll
    for (int j = 1; j < 8; j++) mx = fmaxf(mx, red[j]);
    __syncthreads();
    float sm = 0.f;
#pragma unroll
    for (int e = 0; e < 3; e++) { v[e] = expf(v[e] - mx); sm += v[e]; }
#pragma unroll
    for (int o = 16; o; o >>= 1) sm += __shfl_xor_sync(0xffffffffu, sm, o);
    if ((t & 31) == 0) red[t >> 5] = sm;
    __syncthreads();
    sm = 0.f;
#pragma unroll
    for (int j = 0; j < 8; j++) sm += red[j];
    float inv = 1.f / sm;
#pragma unroll
    for (int e = 0; e < 3; e++) row[t + e * 256] = v[e] * inv * arow[t + e * 256];
}

// ---------------- hs = P^T V  ->  g_H[:,64:128] ----------------
__global__ __launch_bounds__(256) void gemm_pv_kernel() {
    __shared__ float As[16][132];
    __shared__ float Bs[16][68];
    float acc[8][4] = {};
    int t = threadIdx.x, tx = t & 15, ty = t >> 4;
    int m0 = blockIdx.x * 128;
    int bt = blockIdx.z;
    int bb_ = bt / 12, ttime = bt - bb_ * 12;
    int rb = bb_ * NT + ttime;
    const float* Pb = g_P + (size_t)bt * 589824;
    for (int k0 = 0; k0 < 768; k0 += 16) {
#pragma unroll
        for (int e = 0; e < 2; e++) {
            int f = t + e * 256;
            int vl = f >> 5, wg = f & 31;
            *(float4*)&As[vl][wg * 4] = *(const float4*)&Pb[(size_t)(k0 + vl) * 768 + m0 + wg * 4];
        }
        {
            int vl = t >> 4, cg = t & 15;
            *(float4*)&Bs[vl][cg * 4] =
                *(const float4*)&g_qkvf[(size_t)(rb + (k0 + vl) * 12) * 448 + 256 + cg * 4];
        }
        __syncthreads();
        mm_inner(As, Bs, acc, tx, ty);
        __syncthreads();
    }
#pragma unroll
    for (int ii = 0; ii < 8; ii++) {
        int w = m0 + ty * 8 + ii;
        *(float4*)&g_H[(size_t)(bb_ * NT + w * 12 + ttime) * 128 + 64 + tx * 4] =
            make_float4(acc[ii][0], acc[ii][1], acc[ii][2], acc[ii][3]);
    }
}

// ---------------- time attention 12x12 per (b,n) -> g_H[:,0:64] ----------------
__global__ __launch_bounds__(256) void time_attn_kernel(const float* __restrict__ Bt) {
    __shared__ float qt[12 * 64], kt[12 * 64], vs[12 * 64], sa[144];
    int bn = blockIdx.x;
    int bb_ = bn / 768, n = bn - bb_ * 768;
    int rb = bb_ * NT + n * 12;
    int t = threadIdx.x;
    for (int e = t; e < 768; e += 256) {
        int i = e >> 6, k = e & 63;
        size_t base = (size_t)(rb + i) * 448;
        qt[e] = g_qkvf[base + 128 + k];
        kt[e] = g_qkvf[base + 192 + k];
        vs[e] = g_qkvf[base + 256 + k];
    }
    __syncthreads();
    if (t < 144) {
        int i = t / 12, j = t - 12 * i;
        float s = 0.f;
#pragma unroll
        for (int k = 0; k < 64; k++) s += qt[i * 64 + k] * kt[j * 64 + k];
        sa[t] = s * SCALE + __ldg(&Bt[t]);
    }
    __syncthreads();
    if (t < 12) {
        float m = -1e30f;
#pragma unroll
        for (int j = 0; j < 12; j++) m = fmaxf(m, sa[t * 12 + j]);
        float e_[12]; float Z = 0.f;
#pragma unroll
        for (int j = 0; j < 12; j++) { e_[j] = expf(sa[t * 12 + j] - m); Z += e_[j]; }
        float inv = 1.f / Z;
#pragma unroll
        for (int j = 0; j < 12; j++) sa[t * 12 + j] = e_[j] * inv;
    }
    __syncthreads();
    for (int e = t; e < 768; e += 256) {
        int w = e >> 6, c = e & 63;
        float o = 0.f;
#pragma unroll
        for (int v = 0; v < 12; v++) o += sa[v * 12 + w] * vs[v * 64 + c];
        g_H[(size_t)(rb + w) * 128 + c] = o;
    }
}

// ---------------- proj: xmid = (H*FCV) @ Wp + b + x(residual BCNT) ----------------
__global__ __launch_bounds__(256) void gemm_proj_kernel(const float* __restrict__ x,
                                                        const float* __restrict__ pb) {
    __shared__ float As[16][132];
    __shared__ float Bs[16][68];
    float acc[8][4] = {};
    int t = threadIdx.x, tx = t & 15, ty = t >> 4;
    int m0 = blockIdx.x * 128, n0 = blockIdx.y * 64;
    for (int k0 = 0; k0 < 128; k0 += 16) {
#pragma unroll
        for (int e = 0; e < 2; e++) {
            int f = t + e * 256;
            int row = f >> 2, kg = f & 3;
            size_t p = (size_t)(m0 + row);
            float4 h4 = *(const float4*)&g_H[p * 128 + k0 + kg * 4];
            float4 v4 = *(const float4*)&g_qkvf[p * 448 + 320 + k0 + kg * 4];
            As[kg * 4 + 0][row] = h4.x * v4.x; As[kg * 4 + 1][row] = h4.y * v4.y;
            As[kg * 4 + 2][row] = h4.z * v4.z; As[kg * 4 + 3][row] = h4.w * v4.w;
        }
        {
            int kr = t >> 4, ng = t & 15;
            *(float4*)&Bs[kr][ng * 4] = *(const float4*)&g_wproj[(size_t)(k0 + kr) * 256 + n0 + ng * 4];
        }
        __syncthreads();
        mm_inner(As, Bs, acc, tx, ty);
        __syncthreads();
    }
    int bb_ = m0 / NT;
    int pp = m0 - bb_ * NT + ty * 8;
    const float* xb = x + (size_t)bb_ * CC * NT;
    float fin[8][4];
#pragma unroll
    for (int jj = 0; jj < 4; jj++) {
        int o = n0 + tx * 4 + jj;
        float bv = __ldg(&pb[o]);
        const float* xr = xb + (size_t)o * NT + pp;
#pragma unroll
        for (int ii = 0; ii < 8; ii++) fin[ii][jj] = acc[ii][jj] + bv + xr[ii];
    }
#pragma unroll
    for (int ii = 0; ii < 8; ii++) {
        *(float4*)&g_xmid[(size_t)(m0 + ty * 8 + ii) * 256 + n0 + tx * 4] =
            make_float4(fin[ii][0], fin[ii][1], fin[ii][2], fin[ii][3]);
    }
}

// ---------------- gate: z = a * gelu_exact(g) ----------------
__global__ __launch_bounds__(256) void gate_kernel() {
    int i = blockIdx.x * blockDim.x + threadIdx.x;
    int p = i >> 7, j4 = i & 127;
    const float4* y4 = (const float4*)g_y;
    float4 a = y4[(size_t)p * 256 + j4];
    float4 g = y4[(size_t)p * 256 + 128 + j4];
    float4 z;
    z.x = a.x * (0.5f * g.x * (1.f + erff(g.x * 0.70710678118654752f)));
    z.y = a.y * (0.5f * g.y * (1.f + erff(g.y * 0.70710678118654752f)));
    z.z = a.z * (0.5f * g.z * (1.f + erff(g.z * 0.70710678118654752f)));
    z.w = a.w * (0.5f * g.w * (1.f + erff(g.w * 0.70710678118654752f)));
    ((float4*)g_z)[i] = z;
}

// ---------------- FFN2: out(BCNT) = z @ W2 + b2 + xmid ----------------
__global__ __launch_bounds__(256) void gemm_ffn2_kernel(const float* __restrict__ b2,
                                                        float* __restrict__ out) {
    __shared__ float As[16][132];
    __shared__ float Bs[16][68];
    float acc[8][4] = {};
    int t = threadIdx.x, tx = t & 15, ty = t >> 4;
    int m0 = blockIdx.x * 128, n0 = blockIdx.y * 64;
    for (int k0 = 0; k0 < 512; k0 += 16) {
#pragma unroll
        for (int e = 0; e < 2; e++) {
            int f = t + e * 256;
            int row = f >> 2, kg = f & 3;
            float4 v = *(const float4*)&g_z[(size_t)(m0 + row) * 512 + k0 + kg * 4];
            As[kg * 4 + 0][row] = v.x; As[kg * 4 + 1][row] = v.y;
            As[kg * 4 + 2][row] = v.z; As[kg * 4 + 3][row] = v.w;
        }
        {
            int kr = t >> 4, ng = t & 15;
            *(float4*)&Bs[kr][ng * 4] = *(const float4*)&g_w2p[(size_t)(k0 + kr) * 256 + n0 + ng * 4];
        }
        __syncthreads();
        mm_inner(As, Bs, acc, tx, ty);
        __syncthreads();
    }
    int n = n0 + tx * 4;
    float4 bb4 = *(const float4*)&b2[n];
    float fin[8][4];
#pragma unroll
    for (int ii = 0; ii < 8; ii++) {
        int m = m0 + ty * 8 + ii;
        float4 res = *(const float4*)&g_xmid[(size_t)m * 256 + n];
        fin[ii][0] = acc[ii][0] + bb4.x + res.x;
        fin[ii][1] = acc[ii][1] + bb4.y + res.y;
        fin[ii][2] = acc[ii][2] + bb4.z + res.z;
        fin[ii][3] = acc[ii][3] + bb4.w + res.w;
    }
    int bb_ = m0 / NT;
    int pp = m0 - bb_ * NT + ty * 8;
    float* ob = out + (size_t)bb_ * CC * NT;
#pragma unroll
    for (int jj = 0; jj < 4; jj++) {
        int o = n + jj;
        float* orow = ob + (size_t)o * NT + pp;
        *(float4*)&orow[0] = make_float4(fin[0][jj], fin[1][jj], fin[2][jj], fin[3][jj]);
        *(float4*)&orow[4] = make_float4(fin[4][jj], fin[5][jj], fin[6][jj], fin[7][jj]);
    }
}

extern "C" void kernel_launch(void* const* d_in, const int* in_sizes, int n_in,
                              void* d_out, int out_size) {
    const float* x      = (const float*)d_in[0];
    const float* adj    = (const float*)d_in[4];
    const float* ln1_w  = (const float*)d_in[5];
    const float* ln1_b  = (const float*)d_in[6];
    const float* ln2_w  = (const float*)d_in[7];
    const float* ln2_b  = (const float*)d_in[8];
    const float* Wnq    = (const float*)d_in[9];
    const float* bnq    = (const float*)d_in[10];
    const float* Wnk    = (const float*)d_in[11];
    const float* bnk    = (const float*)d_in[12];
    const float* Wtq    = (const float*)d_in[13];
    const float* btq    = (const float*)d_in[14];
    const float* Wtk    = (const float*)d_in[15];
    const float* btk    = (const float*)d_in[16];
    const float* Bn     = (const float*)d_in[17];
    const float* Bt     = (const float*)d_in[18];
    const float* v_w    = (const float*)d_in[19];
    const float* v_b    = (const float*)d_in[20];
    const float* fcv_w  = (const float*)d_in[21];
    const float* fcv_b  = (const float*)d_in[22];
    const float* proj_w = (const float*)d_in[23];
    const float* proj_b = (const float*)d_in[24];
    const float* w1     = (const float*)d_in[25];
    const float* b1     = (const float*)d_in[26];
    const float* w2     = (const float*)d_in[27];
    const float* b2     = (const float*)d_in[28];
    float* out = (float*)d_out;

    pack_weights<<<256, 256>>>(Wnq, Wnk, Wtq, Wtk, bnq, bnk, btq, btk,
                               v_w, v_b, fcv_w, fcv_b, proj_w, w1, w2);
    ln1_kernel<<<NPOS / 32, 256>>>(x, ln1_w, ln1_b);
    gemm_qkvf_kernel<<<dim3(576, 7), 256>>>();
    gemm_s_kernel<<<dim3(6, 12, 96), 256>>>(Bn);
    softmax_adj_kernel<<<73728, 256>>>(adj);
    gemm_pv_kernel<<<dim3(6, 1, 96), 256>>>();
    time_attn_kernel<<<6144, 256>>>(Bt);
    gemm_proj_kernel<<<dim3(576, 4), 256>>>(x, proj_b);
    ln2_kernel<<<NPOS / 8, 256>>>(ln2_w, ln2_b);
    gemm_ffn1_kernel<<<dim3(576, 16), 256>>>(b1);
    gate_kernel<<<36864, 256>>>();
    gemm_ffn2_kernel<<<dim3(576, 4), 256>>>(b2, out);
}

// round 12
// speedup vs baseline: 1.0037x; 1.0037x over previous
#include <cuda_runtime.h>
#include <math.h>

#define CC    256
#define NNODE 768
#define TT    12
#define NT    9216
#define NPOS  73728
#define SCALE 0.125f
#define LNEPS 1e-6f

__device__ float g_x1t [NPOS * 256];
__device__ float g_qkvf[(size_t)NPOS * 448];
__device__ float g_P   [(size_t)96 * 768 * 768];
__device__ float g_H   [NPOS * 128];
__device__ float g_xmid[NPOS * 256];
__device__ float g_x2  [NPOS * 256];
__device__ float g_y   [(size_t)NPOS * 1024];
__device__ float g_z   [(size_t)NPOS * 512];
__device__ float g_wqkvf[256 * 448];
__device__ float g_b448 [448];
__device__ float g_wproj[128 * 256];
__device__ float g_w1p  [256 * 1024];
__device__ float g_w2p  [512 * 256];

// ---------------- weight packing (k-major) ----------------
__global__ void pack_weights(const float* __restrict__ Wnq, const float* __restrict__ Wnk,
                             const float* __restrict__ Wtq, const float* __restrict__ Wtk,
                             const float* __restrict__ bnq, const float* __restrict__ bnk,
                             const float* __restrict__ btq, const float* __restrict__ btk,
                             const float* __restrict__ v_w, const float* __restrict__ v_b,
                             const float* __restrict__ fcv_w, const float* __restrict__ fcv_b,
                             const float* __restrict__ proj_w,
                             const float* __restrict__ ffn_w1, const float* __restrict__ ffn_w2) {
    int t = blockIdx.x * blockDim.x + threadIdx.x;
    int stride = gridDim.x * blockDim.x;
    for (int i = t; i < 256 * 448; i += stride) {
        int c = i / 448, o = i % 448; float v;
        if      (o < 64)  v = Wnq[c * 64 + o];
        else if (o < 128) v = Wnk[c * 64 + (o - 64)];
        else if (o < 192) v = Wtq[c * 64 + (o - 128)];
        else if (o < 256) v = Wtk[c * 64 + (o - 192)];
        else if (o < 320) v = v_w[(o - 256) * 256 + c];
        else              v = fcv_w[(o - 320) * 256 + c];
        g_wqkvf[i] = v;
    }
    for (int o = t; o < 448; o += stride) {
        float v;
        if      (o < 64)  v = bnq[o];
        else if (o < 128) v = bnk[o - 64];
        else if (o < 192) v = btq[o - 128];
        else if (o < 256) v = btk[o - 192];
        else if (o < 320) v = v_b[o - 256];
        else              v = fcv_b[o - 320];
        g_b448[o] = v;
    }
    for (int i = t; i < 128 * 256; i += stride) { int k = i / 256, o = i % 256; g_wproj[i] = proj_w[o * 128 + k]; }
    for (int i = t; i < 256 * 1024; i += stride) { int k = i / 1024, o = i % 1024; g_w1p[i] = ffn_w1[o * 256 + k]; }
    for (int i = t; i < 512 * 256; i += stride) { int k = i / 256, o = i % 256; g_w2p[i] = ffn_w2[o * 512 + k]; }
}

// ---------------- LN1 + transpose to position-major ----------------
__global__ __launch_bounds__(256) void ln1_kernel(const float* __restrict__ x,
                                                  const float* __restrict__ w,
                                                  const float* __restrict__ b) {
    __shared__ float s[256 * 33];
    __shared__ float psum[256], psq[256];
    __shared__ float mq[32], rq[32];
    int t = threadIdx.x;
    int p0 = blockIdx.x * 32;
    int bidx = p0 / NT;
    int pp0 = p0 - bidx * NT;
    const float* xb = x + (size_t)bidx * CC * NT + pp0;
#pragma unroll
    for (int i = 0; i < 32; i++) {
        int e = t + i * 256;
        int c = e >> 5, q = e & 31;
        s[c * 33 + q] = xb[(size_t)c * NT + q];
    }
    __syncthreads();
    {
        int q = t & 31, part = t >> 5;
        float sm = 0.f, sq = 0.f;
#pragma unroll
        for (int j = 0; j < 32; j++) {
            float v = s[(part * 32 + j) * 33 + q];
            sm += v; sq += v * v;
        }
        psum[t] = sm; psq[t] = sq;
    }
    __syncthreads();
    if (t < 32) {
        float S = 0.f, Q = 0.f;
#pragma unroll
        for (int p = 0; p < 8; p++) { S += psum[p * 32 + t]; Q += psq[p * 32 + t]; }
        float mean = S * (1.f / 256.f);
        float var  = Q * (1.f / 256.f) - mean * mean;
        mq[t] = mean;
        rq[t] = rsqrtf(fmaxf(var, 0.f) + LNEPS);
    }
    __syncthreads();
    int wrp = t >> 5, lane = t & 31;
#pragma unroll
    for (int u = 0; u < 4; u++) {
        int q = wrp * 4 + u;
        float mean = mq[q], rstd = rq[q];
        float* outr = g_x1t + (size_t)(p0 + q) * 256;
#pragma unroll
        for (int j = 0; j < 8; j++) {
            int c = lane + j * 32;
            outr[c] = (s[c * 33 + q] - mean) * rstd * __ldg(&w[c]) + __ldg(&b[c]);
        }
    }
}

// ---------------- LN2 on position-major rows ----------------
__global__ __launch_bounds__(256) void ln2_kernel(const float* __restrict__ w,
                                                  const float* __restrict__ b) {
    int row = blockIdx.x * 8 + (threadIdx.x >> 5);
    int lane = threadIdx.x & 31;
    const float4* r4 = (const float4*)(g_xmid + (size_t)row * 256);
    float4 v0 = r4[lane * 2];
    float4 v1 = r4[lane * 2 + 1];
    float sm = v0.x + v0.y + v0.z + v0.w + v1.x + v1.y + v1.z + v1.w;
    float sq = v0.x*v0.x + v0.y*v0.y + v0.z*v0.z + v0.w*v0.w
             + v1.x*v1.x + v1.y*v1.y + v1.z*v1.z + v1.w*v1.w;
#pragma unroll
    for (int o = 16; o; o >>= 1) {
        sm += __shfl_xor_sync(0xffffffffu, sm, o);
        sq += __shfl_xor_sync(0xffffffffu, sq, o);
    }
    float mean = sm * (1.f / 256.f);
    float var  = sq * (1.f / 256.f) - mean * mean;
    float rstd = rsqrtf(fmaxf(var, 0.f) + LNEPS);
    const float4* w4 = (const float4*)w;
    const float4* b4 = (const float4*)b;
    float4* o4 = (float4*)(g_x2 + (size_t)row * 256);
    float4 ww = w4[lane * 2], bb = b4[lane * 2], r;
    r.x = (v0.x - mean) * rstd * ww.x + bb.x;
    r.y = (v0.y - mean) * rstd * ww.y + bb.y;
    r.z = (v0.z - mean) * rstd * ww.z + bb.z;
    r.w = (v0.w - mean) * rstd * ww.w + bb.w;
    o4[lane * 2] = r;
    ww = w4[lane * 2 + 1]; bb = b4[lane * 2 + 1];
    r.x = (v1.x - mean) * rstd * ww.x + bb.x;
    r.y = (v1.y - mean) * rstd * ww.y + bb.y;
    r.z = (v1.z - mean) * rstd * ww.z + bb.z;
    r.w = (v1.w - mean) * rstd * ww.w + bb.w;
    o4[lane * 2 + 1] = r;
}

// ---------------- SGEMM core: BM=128 BN=64 BK=16, 256thr, 8x4/thr ----------------
__device__ __forceinline__ void mm_inner(float As[][132], float Bs[][68],
                                         float acc[8][4], int tx, int ty) {
#pragma unroll
    for (int kk = 0; kk < 16; kk++) {
        float4 a0 = *(const float4*)&As[kk][ty * 8];
        float4 a1 = *(const float4*)&As[kk][ty * 8 + 4];
        float4 b0 = *(const float4*)&Bs[kk][tx * 4];
        float av[8] = {a0.x, a0.y, a0.z, a0.w, a1.x, a1.y, a1.z, a1.w};
        float bv[4] = {b0.x, b0.y, b0.z, b0.w};
#pragma unroll
        for (int ii = 0; ii < 8; ii++) {
            float a = av[ii];
#pragma unroll
            for (int jj = 0; jj < 4; jj++) acc[ii][jj] = fmaf(a, bv[jj], acc[ii][jj]);
        }
    }
}

__device__ __forceinline__ void gemm_bias_body(const float* __restrict__ A,
                                               const float* __restrict__ W,
                                               const float* __restrict__ bias,
                                               float* __restrict__ out,
                                               int Nn, int K) {
    __shared__ float As[16][132];
    __shared__ float Bs[16][68];
    float acc[8][4] = {};
    int t = threadIdx.x, tx = t & 15, ty = t >> 4;
    int m0 = blockIdx.x * 128, n0 = blockIdx.y * 64;
    for (int k0 = 0; k0 < K; k0 += 16) {
#pragma unroll
        for (int e = 0; e < 2; e++) {
            int f = t + e * 256;
            int row = f >> 2, kg = f & 3;
            float4 v = *(const float4*)&A[(size_t)(m0 + row) * K + k0 + kg * 4];
            As[kg * 4 + 0][row] = v.x; As[kg * 4 + 1][row] = v.y;
            As[kg * 4 + 2][row] = v.z; As[kg * 4 + 3][row] = v.w;
        }
        {
            int kr = t >> 4, ng = t & 15;
            *(float4*)&Bs[kr][ng * 4] = *(const float4*)&W[(size_t)(k0 + kr) * Nn + n0 + ng * 4];
        }
        __syncthreads();
        mm_inner(As, Bs, acc, tx, ty);
        __syncthreads();
    }
    int n = n0 + tx * 4;
    float4 bb = *(const float4*)&bias[n];
#pragma unroll
    for (int ii = 0; ii < 8; ii++) {
        int m = m0 + ty * 8 + ii;
        *(float4*)&out[(size_t)m * Nn + n] =
            make_float4(acc[ii][0] + bb.x, acc[ii][1] + bb.y, acc[ii][2] + bb.z, acc[ii][3] + bb.w);
    }
}

__global__ __launch_bounds__(256) void gemm_qkvf_kernel() {
    gemm_bias_body(g_x1t, g_wqkvf, g_b448, g_qkvf, 448, 256);
}
__global__ __launch_bounds__(256) void gemm_ffn1_kernel(const float* __restrict__ b1) {
    gemm_bias_body(g_x2, g_w1p, b1, g_y, 1024, 256);
}

// ---------------- node attn scores: S = Qn Kn^T * scale + Bn ----------------
__global__ __launch_bounds__(256) void gemm_s_kernel(const float* __restrict__ Bn) {
    __shared__ float As[16][132];
    __shared__ float Bs[16][68];
    float acc[8][4] = {};
    int t = threadIdx.x, tx = t & 15, ty = t >> 4;
    int m0 = blockIdx.x * 128, n0 = blockIdx.y * 64;
    int bt = blockIdx.z;
    int bb_ = bt / 12, ttime = bt - bb_ * 12;
    int rb = bb_ * NT + ttime;
    for (int k0 = 0; k0 < 64; k0 += 16) {
#pragma unroll
        for (int e = 0; e < 2; e++) {
            int f = t + e * 256;
            int row = f >> 2, kg = f & 3;
            float4 v = *(const float4*)&g_qkvf[(size_t)(rb + (m0 + row) * 12) * 448 + k0 + kg * 4];
            As[kg * 4 + 0][row] = v.x; As[kg * 4 + 1][row] = v.y;
            As[kg * 4 + 2][row] = v.z; As[kg * 4 + 3][row] = v.w;
        }
        {
            int jl = t >> 2, kg = t & 3;
            float4 v = *(const float4*)&g_qkvf[(size_t)(rb + (n0 + jl) * 12) * 448 + 64 + k0 + kg * 4];
            Bs[kg * 4 + 0][jl] = v.x; Bs[kg * 4 + 1][jl] = v.y;
            Bs[kg * 4 + 2][jl] = v.z; Bs[kg * 4 + 3][jl] = v.w;
        }
        __syncthreads();
        mm_inner(As, Bs, acc, tx, ty);
        __syncthreads();
    }
    float* Pb = g_P + (size_t)bt * 589824;
    int n = n0 + tx * 4;
#pragma unroll
    for (int ii = 0; ii < 8; ii++) {
        int i = m0 + ty * 8 + ii;
        float4 bnv = *(const float4*)&Bn[(size_t)i * 768 + n];
        *(float4*)&Pb[(size_t)i * 768 + n] =
            make_float4(acc[ii][0] * SCALE + bnv.x, acc[ii][1] * SCALE + bnv.y,
                        acc[ii][2] * SCALE + bnv.z, acc[ii][3] * SCALE + bnv.w);
    }
}

// ---------------- row softmax * adj in place ----------------
__global__ __launch_bounds__(256) void softmax_adj_kernel(const float* __restrict__ adj) {
    __shared__ float red[8];
    size_t r = blockIdx.x;
    float* row = g_P + r * 768;
    const float* arow = adj + r * 768;
    int t = threadIdx.x;
    float v[3];
    float mx = -1e30f;
#pragma unroll
    for (int e = 0; e < 3; e++) { v[e] = row[t + e * 256]; mx = fmaxf(mx, v[e]); }
#pragma unroll
    for (int o = 16; o; o >>= 1) mx = fmaxf(mx, __shfl_xor_sync(0xffffffffu, mx, o));
    if ((t & 31) == 0) red[t >> 5] = mx;
    __syncthreads();
    mx = red[0];
#pragma unroll
    for (int j = 1; j < 8; j++) mx = fmaxf(mx, red[j]);
    __syncthreads();
    float sm = 0.f;
#pragma unroll
    for (int e = 0; e < 3; e++) { v[e] = expf(v[e] - mx); sm += v[e]; }
#pragma unroll
    for (int o = 16; o; o >>= 1) sm += __shfl_xor_sync(0xffffffffu, sm, o);
    if ((t & 31) == 0) red[t >> 5] = sm;
    __syncthreads();
    sm = 0.f;
#pragma unroll
    for (int j = 0; j < 8; j++) sm += red[j];
    float inv = 1.f / sm;
#pragma unroll
    for (int e = 0; e < 3; e++) row[t + e * 256] = v[e] * inv * arow[t + e * 256];
}

// ---------------- hs = P^T V  ->  g_H[:,64:128] ----------------
__global__ __launch_bounds__(256) void gemm_pv_kernel() {
    __shared__ float As[16][132];
    __shared__ float Bs[16][68];
    float acc[8][4] = {};
    int t = threadIdx.x, tx = t & 15, ty = t >> 4;
    int m0 = blockIdx.x * 128;
    int bt = blockIdx.z;
    int bb_ = bt / 12, ttime = bt - bb_ * 12;
    int rb = bb_ * NT + ttime;
    const float* Pb = g_P + (size_t)bt * 589824;
    for (int k0 = 0; k0 < 768; k0 += 16) {
#pragma unroll
        for (int e = 0; e < 2; e++) {
            int f = t + e * 256;
            int vl = f >> 5, wg = f & 31;
            *(float4*)&As[vl][wg * 4] = *(const float4*)&Pb[(size_t)(k0 + vl) * 768 + m0 + wg * 4];
        }
        {
            int vl = t >> 4, cg = t & 15;
            *(float4*)&Bs[vl][cg * 4] =
                *(const float4*)&g_qkvf[(size_t)(rb + (k0 + vl) * 12) * 448 + 256 + cg * 4];
        }
        __syncthreads();
        mm_inner(As, Bs, acc, tx, ty);
        __syncthreads();
    }
#pragma unroll
    for (int ii = 0; ii < 8; ii++) {
        int w = m0 + ty * 8 + ii;
        *(float4*)&g_H[(size_t)(bb_ * NT + w * 12 + ttime) * 128 + 64 + tx * 4] =
            make_float4(acc[ii][0], acc[ii][1], acc[ii][2], acc[ii][3]);
    }
}

// ---------------- time attention 12x12 per (b,n) -> g_H[:,0:64] ----------------
__global__ __launch_bounds__(256) void time_attn_kernel(const float* __restrict__ Bt) {
    __shared__ float qt[12 * 64], kt[12 * 64], vs[12 * 64], sa[144];
    int bn = blockIdx.x;
    int bb_ = bn / 768, n = bn - bb_ * 768;
    int rb = bb_ * NT + n * 12;
    int t = threadIdx.x;
    for (int e = t; e < 768; e += 256) {
        int i = e >> 6, k = e & 63;
        size_t base = (size_t)(rb + i) * 448;
        qt[e] = g_qkvf[base + 128 + k];
        kt[e] = g_qkvf[base + 192 + k];
        vs[e] = g_qkvf[base + 256 + k];
    }
    __syncthreads();
    if (t < 144) {
        int i = t / 12, j = t - 12 * i;
        float s = 0.f;
#pragma unroll
        for (int k = 0; k < 64; k++) s += qt[i * 64 + k] * kt[j * 64 + k];
        sa[t] = s * SCALE + __ldg(&Bt[t]);
    }
    __syncthreads();
    if (t < 12) {
        float m = -1e30f;
#pragma unroll
        for (int j = 0; j < 12; j++) m = fmaxf(m, sa[t * 12 + j]);
        float e_[12]; float Z = 0.f;
#pragma unroll
        for (int j = 0; j < 12; j++) { e_[j] = expf(sa[t * 12 + j] - m); Z += e_[j]; }
        float inv = 1.f / Z;
#pragma unroll
        for (int j = 0; j < 12; j++) sa[t * 12 + j] = e_[j] * inv;
    }
    __syncthreads();
    for (int e = t; e < 768; e += 256) {
        int w = e >> 6, c = e & 63;
        float o = 0.f;
#pragma unroll
        for (int v = 0; v < 12; v++) o += sa[v * 12 + w] * vs[v * 64 + c];
        g_H[(size_t)(rb + w) * 128 + c] = o;
    }
}

// ---------------- proj: xmid = (H*FCV) @ Wp + b + x(residual BCNT) ----------------
__global__ __launch_bounds__(256) void gemm_proj_kernel(const float* __restrict__ x,
                                                        const float* __restrict__ pb) {
    __shared__ float As[16][132];
    __shared__ float Bs[16][68];
    float acc[8][4] = {};
    int t = threadIdx.x, tx = t & 15, ty = t >> 4;
    int m0 = blockIdx.x * 128, n0 = blockIdx.y * 64;
    for (int k0 = 0; k0 < 128; k0 += 16) {
#pragma unroll
        for (int e = 0; e < 2; e++) {
            int f = t + e * 256;
            int row = f >> 2, kg = f & 3;
            size_t p = (size_t)(m0 + row);
            float4 h4 = *(const float4*)&g_H[p * 128 + k0 + kg * 4];
            float4 v4 = *(const float4*)&g_qkvf[p * 448 + 320 + k0 + kg * 4];
            As[kg * 4 + 0][row] = h4.x * v4.x; As[kg * 4 + 1][row] = h4.y * v4.y;
            As[kg * 4 + 2][row] = h4.z * v4.z; As[kg * 4 + 3][row] = h4.w * v4.w;
        }
        {
            int kr = t >> 4, ng = t & 15;
            *(float4*)&Bs[kr][ng * 4] = *(const float4*)&g_wproj[(size_t)(k0 + kr) * 256 + n0 + ng * 4];
        }
        __syncthreads();
        mm_inner(As, Bs, acc, tx, ty);
        __syncthreads();
    }
    int bb_ = m0 / NT;
    int pp = m0 - bb_ * NT + ty * 8;
    const float* xb = x + (size_t)bb_ * CC * NT;
    float fin[8][4];
#pragma unroll
    for (int jj = 0; jj < 4; jj++) {
        int o = n0 + tx * 4 + jj;
        float bv = __ldg(&pb[o]);
        const float* xr = xb + (size_t)o * NT + pp;
#pragma unroll
        for (int ii = 0; ii < 8; ii++) fin[ii][jj] = acc[ii][jj] + bv + xr[ii];
    }
#pragma unroll
    for (int ii = 0; ii < 8; ii++) {
        *(float4*)&g_xmid[(size_t)(m0 + ty * 8 + ii) * 256 + n0 + tx * 4] =
            make_float4(fin[ii][0], fin[ii][1], fin[ii][2], fin[ii][3]);
    }
}

// ---------------- gate: z = a * gelu_exact(g) ----------------
__global__ __launch_bounds__(256) void gate_kernel() {
    int i = blockIdx.x * blockDim.x + threadIdx.x;
    int p = i >> 7, j4 = i & 127;
    const float4* y4 = (const float4*)g_y;
    float4 a = y4[(size_t)p * 256 + j4];
    float4 g = y4[(size_t)p * 256 + 128 + j4];
    float4 z;
    z.x = a.x * (0.5f * g.x * (1.f + erff(g.x * 0.70710678118654752f)));
    z.y = a.y * (0.5f * g.y * (1.f + erff(g.y * 0.70710678118654752f)));
    z.z = a.z * (0.5f * g.z * (1.f + erff(g.z * 0.70710678118654752f)));
    z.w = a.w * (0.5f * g.w * (1.f + erff(g.w * 0.70710678118654752f)));
    ((float4*)g_z)[i] = z;
}

// ---------------- FFN2: out(BCNT) = z @ W2 + b2 + xmid ----------------
__global__ __launch_bounds__(256) void gemm_ffn2_kernel(const float* __restrict__ b2,
                                                        float* __restrict__ out) {
    __shared__ float As[16][132];
    __shared__ float Bs[16][68];
    float acc[8][4] = {};
    int t = threadIdx.x, tx = t & 15, ty = t >> 4;
    int m0 = blockIdx.x * 128, n0 = blockIdx.y * 64;
    for (int k0 = 0; k0 < 512; k0 += 16) {
#pragma unroll
        for (int e = 0; e < 2; e++) {
            int f = t + e * 256;
            int row = f >> 2, kg = f & 3;
            float4 v = *(const float4*)&g_z[(size_t)(m0 + row) * 512 + k0 + kg * 4];
            As[kg * 4 + 0][row] = v.x; As[kg * 4 + 1][row] = v.y;
            As[kg * 4 + 2][row] = v.z; As[kg * 4 + 3][row] = v.w;
        }
        {
            int kr = t >> 4, ng = t & 15;
            *(float4*)&Bs[kr][ng * 4] = *(const float4*)&g_w2p[(size_t)(k0 + kr) * 256 + n0 + ng * 4];
        }
        __syncthreads();
        mm_inner(As, Bs, acc, tx, ty);
        __syncthreads();
    }
    int n = n0 + tx * 4;
    float4 bb4 = *(const float4*)&b2[n];
    float fin[8][4];
#pragma unroll
    for (int ii = 0; ii < 8; ii++) {
        int m = m0 + ty * 8 + ii;
        float4 res = *(const float4*)&g_xmid[(size_t)m * 256 + n];
        fin[ii][0] = acc[ii][0] + bb4.x + res.x;
        fin[ii][1] = acc[ii][1] + bb4.y + res.y;
        fin[ii][2] = acc[ii][2] + bb4.z + res.z;
        fin[ii][3] = acc[ii][3] + bb4.w + res.w;
    }
    int bb_ = m0 / NT;
    int pp = m0 - bb_ * NT + ty * 8;
    float* ob = out + (size_t)bb_ * CC * NT;
#pragma unroll
    for (int jj = 0; jj < 4; jj++) {
        int o = n + jj;
        float* orow = ob + (size_t)o * NT + pp;
        *(float4*)&orow[0] = make_float4(fin[0][jj], fin[1][jj], fin[2][jj], fin[3][jj]);
        *(float4*)&orow[4] = make_float4(fin[4][jj], fin[5][jj], fin[6][jj], fin[7][jj]);
    }
}

extern "C" void kernel_launch(void* const* d_in, const int* in_sizes, int n_in,
                              void* d_out, int out_size) {
    const float* x      = (const float*)d_in[0];
    const float* adj    = (const float*)d_in[4];
    const float* ln1_w  = (const float*)d_in[5];
    const float* ln1_b  = (const float*)d_in[6];
    const float* ln2_w  = (const float*)d_in[7];
    const float* ln2_b  = (const float*)d_in[8];
    const float* Wnq    = (const float*)d_in[9];
    const float* bnq    = (const float*)d_in[10];
    const float* Wnk    = (const float*)d_in[11];
    const float* bnk    = (const float*)d_in[12];
    const float* Wtq    = (const float*)d_in[13];
    const float* btq    = (const float*)d_in[14];
    const float* Wtk    = (const float*)d_in[15];
    const float* btk    = (const float*)d_in[16];
    const float* Bn     = (const float*)d_in[17];
    const float* Bt     = (const float*)d_in[18];
    const float* v_w    = (const float*)d_in[19];
    const float* v_b    = (const float*)d_in[20];
    const float* fcv_w  = (const float*)d_in[21];
    const float* fcv_b  = (const float*)d_in[22];
    const float* proj_w = (const float*)d_in[23];
    const float* proj_b = (const float*)d_in[24];
    const float* w1     = (const float*)d_in[25];
    const float* b1     = (const float*)d_in[26];
    const float* w2     = (const float*)d_in[27];
    const float* b2     = (const float*)d_in[28];
    float* out = (float*)d_out;

    pack_weights<<<256, 256>>>(Wnq, Wnk, Wtq, Wtk, bnq, bnk, btq, btk,
                               v_w, v_b, fcv_w, fcv_b, proj_w, w1, w2);
    ln1_kernel<<<NPOS / 32, 256>>>(x, ln1_w, ln1_b);
    gemm_qkvf_kernel<<<dim3(576, 7), 256>>>();
    gemm_s_kernel<<<dim3(6, 12, 96), 256>>>(Bn);
    softmax_adj_kernel<<<73728, 256>>>(adj);
    gemm_pv_kernel<<<dim3(6, 1, 96), 256>>>();
    time_attn_kernel<<<6144, 256>>>(Bt);
    gemm_proj_kernel<<<dim3(576, 4), 256>>>(x, proj_b);
    ln2_kernel<<<NPOS / 8, 256>>>(ln2_w, ln2_b);
    gemm_ffn1_kernel<<<dim3(576, 16), 256>>>(b1);
    gate_kernel<<<36864, 256>>>();
    gemm_ffn2_kernel<<<dim3(576, 4), 256>>>(b2, out);
}